// round 1
// baseline (speedup 1.0000x reference)
#include <cuda_runtime.h>

#define T_   4
#define B_   16
#define C_   256
#define N_   1024
#define CH_  1024
#define HEADS 8
#define DHEAD 32

#define S_C   (B_ * C_ * N_)    // 4194304  elements per t, C-channel tensors
#define S_CH  (B_ * CH_ * N_)   // 16777216 elements per t, Ch-channel tensor

// Scratch (static device globals; allocation at module load, allowed by rules)
__device__ float g_xs[(size_t)T_ * S_C];   // spikes of x / reused as y0
__device__ float g_q [(size_t)T_ * S_C];   // q pre/post LIF / reused as z0
__device__ float g_k [(size_t)T_ * S_C];   // k pre/post LIF
__device__ float g_x1[(size_t)T_ * S_C];   // x + attention branch
__device__ float g_z1[(size_t)T_ * S_CH];  // MLP hidden

// ---------------------------------------------------------------------------
// LIF over leading T axis: mem = mem*0.5 + x; s = (mem >= thr); mem *= (1-s)
// ---------------------------------------------------------------------------
__global__ void lif_kernel(const float* __restrict__ in, float* __restrict__ out,
                           float thr, int S) {
    int s = blockIdx.x * blockDim.x + threadIdx.x;
    if (s >= S) return;
    float mem = 0.f;
#pragma unroll
    for (int t = 0; t < T_; t++) {
        float v = mem * 0.5f + in[(size_t)t * S + s];
        float sp = (v >= thr) ? 1.f : 0.f;
        out[(size_t)t * S + s] = sp;
        mem = v * (1.f - sp);
    }
}

// ---------------------------------------------------------------------------
// Batched SGEMM with fused affine epilogue + optional residual:
//   Out[b,m,n] = (sum_k W[m,k]*X[b,k,n] + bias1[m]) * scale[m] + shift[m]
//                (+ res[b,m,n] if res != nullptr)
// Tiles: BM=128, BN=128, BK=8; 256 threads, 8x8 per-thread tile.
// Assumes M%128==0, N%128==0, K%8==0 (true for all shapes here).
// ---------------------------------------------------------------------------
__launch_bounds__(256)
__global__ void sgemm_epi(const float* __restrict__ X, const float* __restrict__ W,
                          float* __restrict__ Out,
                          const float* __restrict__ bias1,
                          const float* __restrict__ scale,
                          const float* __restrict__ shift,
                          const float* __restrict__ res,
                          int M, int K, int N) {
    const int BM = 128, BN = 128, BK = 8;
    __shared__ float Ws[BK][BM];
    __shared__ float Xs[BK][BN];

    int batch = blockIdx.z;
    int m0 = blockIdx.y * BM;
    int n0 = blockIdx.x * BN;
    size_t xbase = (size_t)batch * K * N;
    size_t obase = (size_t)batch * M * N;

    int tid = threadIdx.x;
    int tx = tid & 15;        // N direction (16)
    int ty = tid >> 4;        // M direction (16)

    // staging indices
    int wm = tid >> 1;        // 0..127
    int wk = (tid & 1) * 4;   // 0 or 4
    int xr = tid >> 5;        // 0..7
    int xc = (tid & 31) * 4;  // 0..124

    float acc[8][8];
#pragma unroll
    for (int i = 0; i < 8; i++)
#pragma unroll
        for (int j = 0; j < 8; j++) acc[i][j] = 0.f;

    for (int k0 = 0; k0 < K; k0 += BK) {
        float4 wv = *(const float4*)&W[(size_t)(m0 + wm) * K + k0 + wk];
        Ws[wk + 0][wm] = wv.x;
        Ws[wk + 1][wm] = wv.y;
        Ws[wk + 2][wm] = wv.z;
        Ws[wk + 3][wm] = wv.w;
        float4 xv = *(const float4*)&X[xbase + (size_t)(k0 + xr) * N + n0 + xc];
        *(float4*)&Xs[xr][xc] = xv;
        __syncthreads();
#pragma unroll
        for (int kk = 0; kk < BK; kk++) {
            float a[8], b[8];
            *(float4*)&a[0] = *(const float4*)&Ws[kk][ty * 8];
            *(float4*)&a[4] = *(const float4*)&Ws[kk][ty * 8 + 4];
            *(float4*)&b[0] = *(const float4*)&Xs[kk][tx * 8];
            *(float4*)&b[4] = *(const float4*)&Xs[kk][tx * 8 + 4];
#pragma unroll
            for (int i = 0; i < 8; i++)
#pragma unroll
                for (int j = 0; j < 8; j++) acc[i][j] += a[i] * b[j];
        }
        __syncthreads();
    }

#pragma unroll
    for (int i = 0; i < 8; i++) {
        int m = m0 + ty * 8 + i;
        float bv = bias1 ? bias1[m] : 0.f;
        float sc = scale[m];
        float sh = shift[m];
#pragma unroll
        for (int j = 0; j < 8; j++) {
            int n = n0 + tx * 8 + j;
            float v = (acc[i][j] + bv) * sc + sh;
            size_t o = obase + (size_t)m * N + n;
            if (res) v += res[o];
            Out[o] = v;
        }
    }
}

// ---------------------------------------------------------------------------
// Attention: per (b, head, n):
//   qs[t]   = sum_d q[t,b,head,d,n]
//   msum[0] = qs[0]; msum[t] = a*msum[t-1] + (1-a)*qs[t-1]
//   attn    = LIF(msum + qs, thr=0.5)
//   y0[t,b,head*32+d,n] = attn[t] * k[...]
// ---------------------------------------------------------------------------
__global__ void attn_kernel(const float* __restrict__ q, const float* __restrict__ k,
                            float* __restrict__ y0, const float* __restrict__ alpha_p) {
    int idx = blockIdx.x * blockDim.x + threadIdx.x;
    if (idx >= B_ * HEADS * N_) return;
    int n  = idx & (N_ - 1);
    int hh = (idx >> 10) & (HEADS - 1);
    int b  = idx >> 13;
    float alpha = *alpha_p;

    size_t base = ((size_t)b * C_ + hh * DHEAD) * (size_t)N_ + n;
    const size_t ts = (size_t)S_C;

    float qs[T_];
#pragma unroll
    for (int t = 0; t < T_; t++) {
        float ssum = 0.f;
#pragma unroll
        for (int di = 0; di < DHEAD; di++)
            ssum += q[t * ts + base + (size_t)di * N_];
        qs[t] = ssum;
    }
    float msum[T_];
    msum[0] = qs[0];
#pragma unroll
    for (int t = 1; t < T_; t++)
        msum[t] = alpha * msum[t - 1] + (1.f - alpha) * qs[t - 1];

    float mem = 0.f;
#pragma unroll
    for (int t = 0; t < T_; t++) {
        float v = mem * 0.5f + (msum[t] + qs[t]);
        float sp = (v >= 0.5f) ? 1.f : 0.f;
        mem = v * (1.f - sp);
#pragma unroll
        for (int di = 0; di < DHEAD; di++) {
            size_t o = t * ts + base + (size_t)di * N_;
            y0[o] = sp * k[o];
        }
    }
}

// ---------------------------------------------------------------------------
extern "C" void kernel_launch(void* const* d_in, const int* in_sizes, int n_in,
                              void* d_out, int out_size) {
    const float* x         = (const float*)d_in[0];
    const float* q_w       = (const float*)d_in[1];
    const float* q_g       = (const float*)d_in[2];
    const float* q_b       = (const float*)d_in[3];
    const float* k_w       = (const float*)d_in[4];
    const float* k_g       = (const float*)d_in[5];
    const float* k_b       = (const float*)d_in[6];
    const float* proj_w    = (const float*)d_in[7];
    const float* proj_bias = (const float*)d_in[8];
    const float* proj_g    = (const float*)d_in[9];
    const float* proj_b2   = (const float*)d_in[10];
    const float* mem_alpha = (const float*)d_in[11];
    const float* w1        = (const float*)d_in[12];
    const float* b1        = (const float*)d_in[13];
    const float* bn1_g     = (const float*)d_in[14];
    const float* bn1_b     = (const float*)d_in[15];
    const float* w2        = (const float*)d_in[16];
    const float* b2        = (const float*)d_in[17];
    const float* bn2_g     = (const float*)d_in[18];
    const float* bn2_b     = (const float*)d_in[19];
    float* out = (float*)d_out;

    float *xs, *qb, *kb, *x1, *z1;
    cudaGetSymbolAddress((void**)&xs, g_xs);
    cudaGetSymbolAddress((void**)&qb, g_q);
    cudaGetSymbolAddress((void**)&kb, g_k);
    cudaGetSymbolAddress((void**)&x1, g_x1);
    cudaGetSymbolAddress((void**)&z1, g_z1);

    dim3 lifgrid((S_C + 255) / 256);
    dim3 lifgrid2((S_CH + 255) / 256);
    dim3 gC(N_ / 128, C_ / 128, T_ * B_);   // M=256 GEMMs
    dim3 gH(N_ / 128, CH_ / 128, T_ * B_);  // M=1024 GEMM

    // 1. xs = lif(x)
    lif_kernel<<<lifgrid, 256>>>(x, xs, 1.f, S_C);
    // 2/3. q_pre = bn(q_w @ xs), k_pre = bn(k_w @ xs)
    sgemm_epi<<<gC, 256>>>(xs, q_w, qb, nullptr, q_g, q_b, nullptr, C_, C_, N_);
    sgemm_epi<<<gC, 256>>>(xs, k_w, kb, nullptr, k_g, k_b, nullptr, C_, C_, N_);
    // 4/5. q = lif(q_pre), k = lif(k_pre)   (in place)
    lif_kernel<<<lifgrid, 256>>>(qb, qb, 1.f, S_C);
    lif_kernel<<<lifgrid, 256>>>(kb, kb, 1.f, S_C);
    // 6. attention -> y0 (reuse xs)
    attn_kernel<<<(B_ * HEADS * N_ + 255) / 256, 256>>>(qb, kb, xs, mem_alpha);
    // 7. x1 = x + bn(proj_w @ y0 + proj_bias)
    sgemm_epi<<<gC, 256>>>(xs, proj_w, x1, proj_bias, proj_g, proj_b2, x, C_, C_, N_);
    // 8. z0 = lif(x1) (into qb)
    lif_kernel<<<lifgrid, 256>>>(x1, qb, 1.f, S_C);
    // 9. z1 = bn1(w1 @ z0 + b1)
    sgemm_epi<<<gH, 256>>>(qb, w1, z1, b1, bn1_g, bn1_b, nullptr, CH_, C_, N_);
    // 10. z2 = lif(z1) (in place)
    lif_kernel<<<lifgrid2, 256>>>(z1, z1, 1.f, S_CH);
    // 11. out = x1 + bn2(w2 @ z2 + b2)
    sgemm_epi<<<gC, 256>>>(z1, w2, out, b2, bn2_g, bn2_b, x1, C_, CH_, N_);
}

// round 3
// speedup vs baseline: 2.5681x; 2.5681x over previous
#include <cuda_runtime.h>
#include <cuda_fp16.h>
#include <cstdint>

#define T_ 4
#define B_ 16
#define NN 1024
#define C_ 256
#define CH_ 1024
#define SC (B_*C_*NN)      // 4194304
#define SCH (B_*CH_*NN)    // 16777216

// ---------------- scratch (device globals; no runtime alloc) ----------------
__device__ __half g_xsT[(size_t)T_*SC];
__device__ __half g_qT [(size_t)T_*SC];
__device__ __half g_kT [(size_t)T_*SC];
__device__ __half g_y0T[(size_t)T_*SC];
__device__ __half g_z0T[(size_t)T_*SC];
__device__ __half g_z1T[(size_t)T_*SCH];
__device__ float  g_x1 [(size_t)T_*SC];
__device__ __half g_pq [256*512];
__device__ __half g_pk [256*512];
__device__ __half g_pp [256*512];
__device__ __half g_pw1[1024*512];
__device__ __half g_pw2[256*2048];

// ---------------- helpers ----------------
__device__ __forceinline__ uint32_t smem_u32(const void* p) {
    uint32_t a;
    asm("{ .reg .u64 t; cvta.to.shared.u64 t, %1; cvt.u32.u64 %0, t; }" : "=r"(a) : "l"(p));
    return a;
}
__device__ __forceinline__ void cpasync16(uint32_t dst, const void* src) {
    asm volatile("cp.async.cg.shared.global [%0], [%1], 16;" :: "r"(dst), "l"(src) : "memory");
}
__device__ __forceinline__ void cp_commit() {
    asm volatile("cp.async.commit_group;" ::: "memory");
}
template<int N> __device__ __forceinline__ void cp_wait() {
    asm volatile("cp.async.wait_group %0;" :: "n"(N) : "memory");
}
__device__ __forceinline__ void ldsm4(uint32_t& r0, uint32_t& r1, uint32_t& r2, uint32_t& r3, uint32_t addr) {
    asm volatile("ldmatrix.sync.aligned.m8n8.x4.shared.b16 {%0,%1,%2,%3}, [%4];"
                 : "=r"(r0), "=r"(r1), "=r"(r2), "=r"(r3) : "r"(addr));
}
__device__ __forceinline__ void mma16816(float* d, const uint32_t* a, uint32_t b0, uint32_t b1) {
    asm volatile("mma.sync.aligned.m16n8k16.row.col.f32.f16.f16.f32 "
                 "{%0,%1,%2,%3}, {%4,%5,%6,%7}, {%8,%9}, {%0,%1,%2,%3};"
                 : "+f"(d[0]), "+f"(d[1]), "+f"(d[2]), "+f"(d[3])
                 : "r"(a[0]), "r"(a[1]), "r"(a[2]), "r"(a[3]), "r"(b0), "r"(b1));
}

// packed-A element index: blocked 128(m) x 64(ke) tiles, SW128-swizzled inside.
__device__ __forceinline__ size_t blk_elem(int m, int ke, int nck) {
    int bm = m >> 7, rin = m & 127, kc = ke >> 6, c = ke & 63;
    uint32_t byte = (uint32_t)(rin * 128 + c * 2);
    byte ^= ((byte >> 3) & 0x70);
    return ((size_t)bm * nck + kc) * 8192 + (byte >> 1);
}

// ---------------- weight packer: fp32 W[M,K] -> fp16 {hi,lo} blocked+swizzled ----------------
__global__ void pack_kernel(const float* __restrict__ W, __half* __restrict__ P, int M, int K) {
    int i = blockIdx.x * 256 + threadIdx.x;
    if (i >= M * K) return;
    int m = i / K, k = i % K;
    int nck = (2 * K) >> 6;
    float w = W[i];
    __half hi = __float2half(w);
    float rr = w - __half2float(hi);
    __half lo = __float2half(rr);
    P[blk_elem(m, k, nck)]     = hi;
    P[blk_elem(m, K + k, nck)] = lo;
}

// ---------------- LIF + transpose: fp32 [t,b,c,n] -> fp16 spikes [t,b,n,c] ----------------
__global__ void lif_t_kernel(const float* __restrict__ in, __half* __restrict__ out, int Cdim) {
    __shared__ __half st[4][32][72];
    int n0 = blockIdx.x * 32, c0 = blockIdx.y * 64, b = blockIdx.z;
    int nl = threadIdx.x & 31, cg = threadIdx.x >> 5;
#pragma unroll
    for (int pass = 0; pass < 8; pass++) {
        int cl = pass * 8 + cg;
        int c = c0 + cl;
        float mem = 0.f;
#pragma unroll
        for (int t = 0; t < T_; t++) {
            float v = mem * 0.5f + in[((size_t)(t * B_ + b) * Cdim + c) * NN + n0 + nl];
            float sp = (v >= 1.0f) ? 1.f : 0.f;
            st[t][nl][cl] = __float2half(sp);
            mem = v * (1.f - sp);
        }
    }
    __syncthreads();
    int r = threadIdx.x >> 1, hf = threadIdx.x & 1;
    int t = r >> 5, n = r & 31;
    size_t row = ((size_t)(t * B_ + b) * NN + n0 + n) * Cdim + c0 + hf * 32;
    uint4* d = (uint4*)(out + row);
    const uint4* s = (const uint4*)(&st[t][n][hf * 32]);
#pragma unroll
    for (int i = 0; i < 4; i++) d[i] = s[i];
}

// ---------------- attention (transposed fp16 layout) ----------------
__global__ void attn_kernel(const __half* __restrict__ q, const __half* __restrict__ k,
                            __half* __restrict__ y, const float* __restrict__ alpha_p) {
    int idx = blockIdx.x * 256 + threadIdx.x;
    int h = idx & 7;
    int n = (idx >> 3) & 1023;
    int b = idx >> 13;
    float alpha = *alpha_p;
    size_t basep = ((size_t)(b * NN + n)) * C_ + h * 32;

    float qs[T_];
#pragma unroll
    for (int t = 0; t < T_; t++) {
        const __half2* p = (const __half2*)(q + (size_t)t * SC + basep);
        float s = 0.f;
#pragma unroll
        for (int i = 0; i < 16; i++) {
            float2 f = __half22float2(p[i]);
            s += f.x + f.y;
        }
        qs[t] = s;
    }
    float ms[T_];
    ms[0] = qs[0];
#pragma unroll
    for (int t = 1; t < T_; t++) ms[t] = alpha * ms[t - 1] + (1.f - alpha) * qs[t - 1];

    float mem = 0.f;
#pragma unroll
    for (int t = 0; t < T_; t++) {
        float v = mem * 0.5f + (ms[t] + qs[t]);
        float sp = (v >= 0.5f) ? 1.f : 0.f;
        mem = v * (1.f - sp);
        const uint4* kp = (const uint4*)(k + (size_t)t * SC + basep);
        uint4* yp = (uint4*)(y + (size_t)t * SC + basep);
        if (sp != 0.f) {
#pragma unroll
            for (int i = 0; i < 4; i++) yp[i] = kp[i];
        } else {
            uint4 z = {0, 0, 0, 0};
#pragma unroll
            for (int i = 0; i < 4; i++) yp[i] = z;
        }
    }
}

// ---------------- HMMA GEMM with fused epilogue ----------------
// CTA tile 128(M) x 128(N), BK=64 fp16 (K doubled by hi/lo split).
// 8 warps: 2(M) x 4(N); warp tile 64x32; mma m16n8k16.
// EPI 0: bn affine + LIF -> fp16 spikes transposed [t,b,n,m]
// EPI 1: (d + bias)*scale + shift + res -> fp32 [t,b,m,n]
#define SMEM_EPI0 101376
#define SMEM_EPI1 66560

template<int CSRC, int COUT, int EPI>
__global__ __launch_bounds__(256) void gemm_mma(
    const __half* __restrict__ pack, const __half* __restrict__ XT,
    float* __restrict__ outF, __half* __restrict__ outS,
    const float* __restrict__ bias1, const float* __restrict__ scale,
    const float* __restrict__ shift, const float* __restrict__ res, float thr)
{
    extern __shared__ char smraw[];
    uint32_t smb0 = smem_u32(smraw);
    uint32_t smb = (smb0 + 1023u) & ~1023u;
    char* base = smraw + (smb - smb0);
    const uint32_t OF_A = 0, OF_B = 32768, OF_STG = 65536;

    const int NC = (2 * CSRC) / 64;      // chunks per timestep
    const int G = 4 * NC;                // total chunks
    const int n0g = blockIdx.x * 128;
    const int m0g = blockIdx.y * 128;
    const int b = blockIdx.z;
    const int tid = threadIdx.x;
    const int wid = tid >> 5, lane = tid & 31;
    const int mw = (wid >> 2) * 64, nw = (wid & 3) * 32;
    const int r = lane >> 2, qn = lane & 3;

    // per-thread epilogue params (8 distinct m rows per thread)
    float pb[4][2], psc[4][2], psh[4][2];
#pragma unroll
    for (int mi = 0; mi < 4; mi++)
#pragma unroll
        for (int h = 0; h < 2; h++) {
            int m = m0g + mw + mi * 16 + r + h * 8;
            pb[mi][h]  = bias1 ? bias1[m] : 0.f;
            psc[mi][h] = scale[m];
            psh[mi][h] = shift[m];
        }

    float acc[4][4][4];
    float memv[4][4][4];
#pragma unroll
    for (int mi = 0; mi < 4; mi++)
#pragma unroll
        for (int j = 0; j < 4; j++)
#pragma unroll
            for (int e = 0; e < 4; e++) { acc[mi][j][e] = 0.f; memv[mi][j][e] = 0.f; }

    auto issue = [&](int g) {
        int t = g / NC, kc = g % NC;
        int buf = g & 1;
        // A: linear copy of pre-swizzled 16KB block
        const __half* asrc = pack + ((size_t)blockIdx.y * NC + kc) * 8192 + tid * 32;
        uint32_t adst = smb + OF_A + buf * 16384 + tid * 64;
#pragma unroll
        for (int i = 0; i < 4; i++) cpasync16(adst + i * 16, asrc + i * 8);
        // B: 128 rows x 128B, swizzled dst
        int row = tid >> 1, hf = tid & 1;
        int kb = (kc * 64) % CSRC;
        const __half* bsrc = XT + ((size_t)((t * B_ + b) * NN + n0g + row)) * CSRC + kb + hf * 32;
        uint32_t bb = smb + OF_B + buf * 16384;
#pragma unroll
        for (int i = 0; i < 4; i++) {
            uint32_t byte = (uint32_t)(row * 128 + hf * 64 + i * 16);
            byte ^= ((byte >> 3) & 0x70);
            cpasync16(bb + byte, bsrc + i * 8);
        }
        cp_commit();
    };

    issue(0);
    for (int g = 0; g < G; g++) {
        if (g + 1 < G) { issue(g + 1); cp_wait<1>(); }
        else           { cp_wait<0>(); }
        __syncthreads();

        uint32_t aB = smb + OF_A + (g & 1) * 16384;
        uint32_t bB = smb + OF_B + (g & 1) * 16384;
#pragma unroll
        for (int ks = 0; ks < 4; ks++) {
            uint32_t af[4][4], bf[2][4];
#pragma unroll
            for (int mi = 0; mi < 4; mi++) {
                uint32_t byte = (uint32_t)((mw + mi * 16 + (lane & 15)) * 128 +
                                           (ks * 16 + (lane >> 4) * 8) * 2);
                byte ^= ((byte >> 3) & 0x70);
                ldsm4(af[mi][0], af[mi][1], af[mi][2], af[mi][3], aB + byte);
            }
#pragma unroll
            for (int j2 = 0; j2 < 2; j2++) {
                uint32_t byte = (uint32_t)((nw + j2 * 16 + (lane & 15)) * 128 +
                                           (ks * 16 + (lane >> 4) * 8) * 2);
                byte ^= ((byte >> 3) & 0x70);
                ldsm4(bf[j2][0], bf[j2][1], bf[j2][2], bf[j2][3], bB + byte);
            }
#pragma unroll
            for (int mi = 0; mi < 4; mi++)
#pragma unroll
                for (int j = 0; j < 4; j++)
                    mma16816(acc[mi][j], af[mi], bf[j >> 1][j & 1], bf[j >> 1][(j & 1) + 2]);
        }

        if ((g % NC) == NC - 1) {
            int t = g / NC;
            if (EPI == 0) {
#pragma unroll
                for (int mi = 0; mi < 4; mi++)
#pragma unroll
                    for (int j = 0; j < 4; j++)
#pragma unroll
                        for (int e = 0; e < 4; e++) {
                            int h = e >> 1, eo = e & 1;
                            float v = (acc[mi][j][e] + pb[mi][h]) * psc[mi][h] + psh[mi][h];
                            float u = memv[mi][j][e] * 0.5f + v;
                            float sp = (u >= thr) ? 1.f : 0.f;
                            memv[mi][j][e] = u * (1.f - sp);
                            acc[mi][j][e] = 0.f;
                            int nl = nw + j * 8 + qn * 2 + eo;
                            int ml = mw + mi * 16 + r + h * 8;
                            *(__half*)(base + OF_STG + nl * 272 + ml * 2) = __float2half(sp);
                        }
                __syncthreads();
                {
                    int row = tid >> 1, hf = tid & 1;
                    const uint4* s4 = (const uint4*)(base + OF_STG + row * 272 + hf * 128);
                    uint4* d4 = (uint4*)(outS + ((size_t)((t * B_ + b) * NN + n0g + row)) * COUT
                                               + m0g + hf * 64);
#pragma unroll
                    for (int i = 0; i < 8; i++) d4[i] = s4[i];
                }
            } else {
#pragma unroll
                for (int mi = 0; mi < 4; mi++)
#pragma unroll
                    for (int h = 0; h < 2; h++) {
                        int ml = m0g + mw + mi * 16 + r + h * 8;
                        size_t rowo = ((size_t)((t * B_ + b) * COUT) + ml) * NN + n0g;
#pragma unroll
                        for (int j = 0; j < 4; j++) {
                            size_t o = rowo + nw + j * 8 + qn * 2;
                            float2 rv = *(const float2*)&res[o];
                            float2 ov;
                            ov.x = (acc[mi][j][h * 2 + 0] + pb[mi][h]) * psc[mi][h] + psh[mi][h] + rv.x;
                            ov.y = (acc[mi][j][h * 2 + 1] + pb[mi][h]) * psc[mi][h] + psh[mi][h] + rv.y;
                            *(float2*)&outF[o] = ov;
                            acc[mi][j][h * 2 + 0] = 0.f;
                            acc[mi][j][h * 2 + 1] = 0.f;
                        }
                    }
            }
        }
        __syncthreads();
    }
}

// ---------------- launch ----------------
extern "C" void kernel_launch(void* const* d_in, const int* in_sizes, int n_in,
                              void* d_out, int out_size) {
    const float* x         = (const float*)d_in[0];
    const float* q_w       = (const float*)d_in[1];
    const float* q_g       = (const float*)d_in[2];
    const float* q_b       = (const float*)d_in[3];
    const float* k_w       = (const float*)d_in[4];
    const float* k_g       = (const float*)d_in[5];
    const float* k_b       = (const float*)d_in[6];
    const float* proj_w    = (const float*)d_in[7];
    const float* proj_bias = (const float*)d_in[8];
    const float* proj_g    = (const float*)d_in[9];
    const float* proj_b2   = (const float*)d_in[10];
    const float* mem_alpha = (const float*)d_in[11];
    const float* w1        = (const float*)d_in[12];
    const float* b1        = (const float*)d_in[13];
    const float* bn1_g     = (const float*)d_in[14];
    const float* bn1_b     = (const float*)d_in[15];
    const float* w2        = (const float*)d_in[16];
    const float* b2        = (const float*)d_in[17];
    const float* bn2_g     = (const float*)d_in[18];
    const float* bn2_b     = (const float*)d_in[19];
    float* out = (float*)d_out;

    __half *xsT, *qT, *kT, *y0T, *z0T, *z1T, *pq, *pk, *pp, *pw1, *pw2;
    float* x1;
    cudaGetSymbolAddress((void**)&xsT, g_xsT);
    cudaGetSymbolAddress((void**)&qT,  g_qT);
    cudaGetSymbolAddress((void**)&kT,  g_kT);
    cudaGetSymbolAddress((void**)&y0T, g_y0T);
    cudaGetSymbolAddress((void**)&z0T, g_z0T);
    cudaGetSymbolAddress((void**)&z1T, g_z1T);
    cudaGetSymbolAddress((void**)&x1,  g_x1);
    cudaGetSymbolAddress((void**)&pq,  g_pq);
    cudaGetSymbolAddress((void**)&pk,  g_pk);
    cudaGetSymbolAddress((void**)&pp,  g_pp);
    cudaGetSymbolAddress((void**)&pw1, g_pw1);
    cudaGetSymbolAddress((void**)&pw2, g_pw2);

    cudaFuncSetAttribute(gemm_mma<256, 256, 0>,  cudaFuncAttributeMaxDynamicSharedMemorySize, SMEM_EPI0);
    cudaFuncSetAttribute(gemm_mma<256, 1024, 0>, cudaFuncAttributeMaxDynamicSharedMemorySize, SMEM_EPI0);
    cudaFuncSetAttribute(gemm_mma<256, 256, 1>,  cudaFuncAttributeMaxDynamicSharedMemorySize, SMEM_EPI1);
    cudaFuncSetAttribute(gemm_mma<1024, 256, 1>, cudaFuncAttributeMaxDynamicSharedMemorySize, SMEM_EPI1);

    // pack weights (hi/lo fp16, blocked + swizzled)
    pack_kernel<<<(256 * 256 + 255) / 256, 256>>>(q_w, pq, 256, 256);
    pack_kernel<<<(256 * 256 + 255) / 256, 256>>>(k_w, pk, 256, 256);
    pack_kernel<<<(256 * 256 + 255) / 256, 256>>>(proj_w, pp, 256, 256);
    pack_kernel<<<(1024 * 256 + 255) / 256, 256>>>(w1, pw1, 1024, 256);
    pack_kernel<<<(256 * 1024 + 255) / 256, 256>>>(w2, pw2, 256, 1024);

    dim3 lifg(32, 4, 16);
    dim3 gC(8, 2, 16);
    dim3 gH(8, 8, 16);

    // 1. xsT = lifT(x)
    lif_t_kernel<<<lifg, 256>>>(x, xsT, C_);
    // 2/3. q,k: GEMM + bn + LIF fused -> transposed spikes
    gemm_mma<256, 256, 0><<<gC, 256, SMEM_EPI0>>>(pq, xsT, nullptr, qT, nullptr, q_g, q_b, nullptr, 1.f);
    gemm_mma<256, 256, 0><<<gC, 256, SMEM_EPI0>>>(pk, xsT, nullptr, kT, nullptr, k_g, k_b, nullptr, 1.f);
    // 4. attention
    attn_kernel<<<(B_ * NN * 8) / 256, 256>>>(qT, kT, y0T, mem_alpha);
    // 5. x1 = x + bn(proj @ y0 + proj_bias)
    gemm_mma<256, 256, 1><<<gC, 256, SMEM_EPI1>>>(pp, y0T, x1, nullptr, proj_bias, proj_g, proj_b2, x, 0.f);
    // 6. z0T = lifT(x1)
    lif_t_kernel<<<lifg, 256>>>(x1, z0T, C_);
    // 7. z1T = lif(bn1(w1 @ z0 + b1))  (fused)
    gemm_mma<256, 1024, 0><<<gH, 256, SMEM_EPI0>>>(pw1, z0T, nullptr, z1T, b1, bn1_g, bn1_b, nullptr, 1.f);
    // 8. out = x1 + bn2(w2 @ z1 + b2)
    gemm_mma<1024, 256, 1><<<gC, 256, SMEM_EPI1>>>(pw2, z1T, out, nullptr, b2, bn2_g, bn2_b, x1, 0.f);
}